// round 14
// baseline (speedup 1.0000x reference)
#include <cuda_runtime.h>
#include <cstdint>

#define N 8400
#define WORDS 132          // ceil(8400/64)
#define SCORE_THR 0.5f
#define IOU_THR 0.5f
#define GRID 136           // <= 148 SMs: all blocks co-resident (wave 1)
#define NT 1024
#define JS 32              // rank j-split
#define NPAD 8448          // = 264*32

typedef unsigned long long u64;

struct __align__(16) SpEnt { u64 bits; u64 idx; };

// ---- persistent device state (allocation-free rule) ----
__device__ int g_vcount = 0;
__device__ int g_bar_arrive = 0;
__device__ volatile int g_bar_release = 0;
__device__ int g_bar_exit = 0;
__device__ u64 g_vkey[N];
__device__ float4 g_vbox[N];
__device__ float g_vscore[N];
__device__ int g_rankp[JS][N];
__device__ float4 g_sbox[N];
__device__ float g_sscore[N];
__device__ u64 g_diag2[NPAD][2];           // dense near-diag: own word, next word
__device__ int g_ccount[WORDS];            // CSC: entries per target word
__device__ SpEnt g_clist[WORDS][N];        // CSC: (bits, srcrow) per target word

// Software grid barrier (all CTAs co-resident since GRID < #SMs).
__device__ __forceinline__ void gbar(int gen) {
    __syncthreads();
    if (threadIdx.x == 0) {
        __threadfence();
        int prev = atomicAdd(&g_bar_arrive, 1);
        if (prev == gen * GRID - 1) {
            g_bar_release = gen;
        } else {
            while (g_bar_release < gen) { }
        }
        __threadfence();
    }
    __syncthreads();
}

__device__ __forceinline__ void cpa16(uint32_t saddr, const void* gptr) {
    asm volatile("cp.async.cg.shared.global [%0], [%1], 16;"
                 :: "r"(saddr), "l"(gptr));
}

// batched greedy scan of one 64-row word; kept bit b ORs d0 -> cown, d1 -> cnext
__device__ __forceinline__ void scan_word(const u64 (*sd2)[2], int base, u64 nz,
                                          u64& cown, u64& cnext) {
    u64 cand = nz & ~cown;
    while (cand) {
        int bs[8]; u64 v0[8], v1[8];
        u64 tmp = cand; int m = 0;
#pragma unroll
        for (int k = 0; k < 8; ++k) {
            if (tmp) { bs[k] = __ffsll(tmp) - 1; tmp &= tmp - 1; m = k + 1; }
            else     { bs[k] = 0; }
        }
#pragma unroll
        for (int k = 0; k < 8; ++k) {
            v0[k] = (k < m) ? sd2[base + bs[k]][0] : 0ull;
            v1[k] = (k < m) ? sd2[base + bs[k]][1] : 0ull;
        }
#pragma unroll
        for (int k = 0; k < 8; ++k)
            if (k < m && !((cown >> bs[k]) & 1ull)) { cown |= v0[k]; cnext |= v1[k]; }
        int blast = bs[m - 1];
        u64 below = (blast == 63) ? ~0ull : ((2ull << blast) - 1ull);
        cand = nz & ~cown & ~below;
    }
}

__global__ __launch_bounds__(NT) void k_all(const float* __restrict__ in,
                                            float* __restrict__ out) {
    extern __shared__ __align__(16) char dyn[];   // 135,168B
    __shared__ u64 remv[WORDS + 2];
    __shared__ unsigned s_nz32[2 * WORDS];
    __shared__ int s_cc[WORDS];
    int tid = threadIdx.x;
    int bid = blockIdx.x;
    int gtid = bid * NT + tid;

    // ---------------- Phase 1: decode + compact valid ----------------------
    {
        int a = gtid;
        int lane = tid & 31;
        bool valid = false;
        float4 b = make_float4(0.f, 0.f, 0.f, 0.f);
        float s = 0.f;
        u64 key = 0ull;
        if (a < N) {
            float cx = in[a];
            float cy = in[N + a];
            float w  = in[2 * N + a];
            float h  = in[3 * N + a];
            s = in[4 * N + a];
            float hw = __fmul_rn(w, 0.5f);
            float hh = __fmul_rn(h, 0.5f);
            b.x = __fsub_rn(cx, hw);
            b.y = __fsub_rn(cy, hh);
            b.z = __fadd_rn(cx, hw);
            b.w = __fadd_rn(cy, hh);
            valid = (s >= SCORE_THR);
            key = (((u64)__float_as_uint(s)) << 14) | (u64)(16383 - a);
            g_diag2[a][0] = 0ull;
            g_diag2[a][1] = 0ull;
        }
        if (gtid < WORDS) g_ccount[gtid] = 0;      // reset CSC counters
        unsigned m = __ballot_sync(0xffffffffu, valid);
        if (m != 0u) {
            int leader = __ffs(m) - 1;
            int base = 0;
            if (lane == leader) base = atomicAdd(&g_vcount, __popc(m));
            base = __shfl_sync(0xffffffffu, base, leader);
            if (valid) {
                int pos = base + __popc(m & ((1u << lane) - 1u));
                g_vkey[pos]   = key;
                g_vbox[pos]   = b;
                g_vscore[pos] = s;
            }
        }
    }
    gbar(1);
    int V = *(volatile int*)&g_vcount;

    // ---------------- Phase 2: rank partials (i-blocks x 32 j-chunks) ------
    {
        u64* sk = (u64*)dyn;
        int IB = (V + NT - 1) / NT;
        int CH = (V + JS - 1) / JS;
        int ntasks = IB * JS;
        for (int task = bid; task < ntasks; task += GRID) {
            int ib = task % IB;
            int jb = task / IB;
            int jlo = jb * CH;
            int mlen = min(jlo + CH, V) - jlo;
            __syncthreads();
            for (int d = tid; d < mlen; d += NT)
                sk[d] = g_vkey[jlo + d];
            __syncthreads();
            int p = ib * NT + tid;
            u64 kp = (p < V) ? g_vkey[p] : 0ull;
            int cnt = 0;
#pragma unroll 8
            for (int d = 0; d < mlen; ++d)
                cnt += (sk[d] > kp) ? 1 : 0;
            if (p < V) g_rankp[jb][p] = cnt;
        }
    }
    gbar(2);

    // ---------------- Phase 3: sum partials + scatter -----------------------
    for (int p = gtid; p < V; p += GRID * NT) {
        int r = 0;
#pragma unroll
        for (int y = 0; y < JS; ++y) r += g_rankp[y][p];
        g_sbox[r]   = g_vbox[p];
        g_sscore[r] = g_vscore[p];
    }
    gbar(3);

    // ---------------- Phase 4: IoU -> diag2 + CSC far entries --------------
    {
        float4* cbox  = (float4*)dyn;              // 512 boxes
        float*  carea = (float*)(dyn + 512 * 16);
        int TvR = (V + 127) >> 7;
        int TvC = (V + 511) >> 9;
        int ntasks = 0;
        for (int rb = 0; rb < TvR; ++rb) ntasks += TvC - (rb >> 2);
        for (int task = bid; task < ntasks; task += GRID) {
            int rem = task, rb = 0;
            while (rem >= TvC - (rb >> 2)) { rem -= TvC - (rb >> 2); rb++; }
            int cB = (rb >> 2) + rem;
            __syncthreads();
            if (tid < 512) {
                int j = cB * 512 + tid;
                if (j < V) {
                    float4 b = g_sbox[j];
                    cbox[tid] = b;
                    carea[tid] = __fmul_rn(__fsub_rn(b.z, b.x),
                                           __fsub_rn(b.w, b.y));
                } else {
                    cbox[tid] = make_float4(0.f, 0.f, 0.f, 0.f);
                    carea[tid] = 0.f;
                }
            }
            __syncthreads();
            int row = tid & 127;
            int wq  = tid >> 7;
            int i = rb * 128 + row;
            int wg = cB * 8 + wq;
            int dstart = max(0, i + 1 - wg * 64);
            if (i < V && dstart < 64) {
                float4 bi = g_sbox[i];
                float ai = __fmul_rn(__fsub_rn(bi.z, bi.x),
                                     __fsub_rn(bi.w, bi.y));
                int cbase = wq * 64;
                u64 bits = 0ull;
                for (int d = dstart; d < 64; ++d) {
                    float4 bj = cbox[cbase + d];
                    float ltx = fmaxf(bi.x, bj.x);
                    float lty = fmaxf(bi.y, bj.y);
                    float rbx = fminf(bi.z, bj.z);
                    float rby = fminf(bi.w, bj.w);
                    float wx = fmaxf(__fsub_rn(rbx, ltx), 0.0f);
                    float wy = fmaxf(__fsub_rn(rby, lty), 0.0f);
                    float inter = __fmul_rn(wx, wy);
                    float uni = __fsub_rn(__fadd_rn(ai, carea[cbase + d]), inter);
                    float den = fmaxf(uni, 1e-9f);
                    bool hit;
                    if (inter > __fmul_rn(0.5005f, den))      hit = true;
                    else if (inter < __fmul_rn(0.4995f, den)) hit = false;
                    else hit = (__fdiv_rn(inter, den) > IOU_THR);
                    if (hit) bits |= (1ull << d);
                }
                int own = i >> 6;
                if (wg == own) {
                    g_diag2[i][0] = bits;
                } else if (wg == own + 1) {
                    g_diag2[i][1] = bits;
                } else if (bits) {
                    int pos = atomicAdd(&g_ccount[wg], 1);
                    SpEnt e; e.bits = bits; e.idx = (u64)i;
                    g_clist[wg][pos] = e;
                }
            }
        }
    }
    gbar(4);

    // ---------------- Phase 5: block 0 — CSC-gather reduce + output --------
    if (bid != 0) {
        __syncthreads();
        if (tid == 0) atomicAdd(&g_bar_exit, 1);
        return;
    }

    u64 (*sd2)[2] = (u64 (*)[2])dyn;               // [NPAD][2] 135,168B
    int T = (V + 63) >> 6;
    int TT = (T + 1) >> 1;
    __syncthreads();
    // init remv (incl. 2 spill words): bit p set iff p >= V
    for (int w = tid; w < WORDS + 2; w += NT) {
        int base = w * 64;
        u64 m;
        if (base + 64 <= V)      m = 0ull;
        else if (base >= V)      m = ~0ull;
        else                     m = (~0ull) << (V - base);
        remv[w] = m;
    }
    if (tid < WORDS) s_cc[tid] = g_ccount[tid];
    // one-shot staging: diag2 rows [0,V)
    {
        for (int u = tid; u < V; u += NT)
            cpa16((uint32_t)__cvta_generic_to_shared(&sd2[u][0]), &g_diag2[u][0]);
        asm volatile("cp.async.commit_group;");
        asm volatile("cp.async.wait_group 0;" ::: "memory");
    }
    __syncthreads();
    // nz bitmap over (d0|d1), bounded to NPAD
    for (int c = 0; c < NPAD; c += NT) {
        int r = c + tid;
        bool nzb = (r < V) && ((sd2[r][0] | sd2[r][1]) != 0ull);
        unsigned bal = __ballot_sync(0xffffffffu, nzb);
        if ((tid & 31) == 0 && r < NPAD) s_nz32[r >> 5] = bal;
    }
    __syncthreads();

    int lane = tid & 31;
    for (int t = 0; t < TT; ++t) {
        int w0 = 2 * t, w1 = 2 * t + 1;
        // ---- CSC gather: far contributions to w0/w1 from kept earlier rows
        {
            int cnt0 = s_cc[w0];
            int cnt1 = (w1 < T) ? s_cc[w1] : 0;
            int total = cnt0 + cnt1;
            u64 a0 = 0ull, a1 = 0ull;
            for (int e = tid; e < total; e += NT) {
                bool second = (e >= cnt0);
                const SpEnt* lp = second ? &g_clist[w1][e - cnt0]
                                         : &g_clist[w0][e];
                ulonglong2 ent = *(const ulonglong2*)lp;      // LDG.128
                int sr = (int)ent.y;                          // src row (< w0*64)
                bool kept = !((remv[sr >> 6] >> (sr & 63)) & 1ull);
                if (kept) { if (second) a1 |= ent.x; else a0 |= ent.x; }
            }
            // warp OR-reduce, then <= 2 atomics per warp
#pragma unroll
            for (int o = 16; o > 0; o >>= 1) {
                a0 |= __shfl_xor_sync(0xffffffffu, a0, o);
                a1 |= __shfl_xor_sync(0xffffffffu, a1, o);
            }
            if (lane == 0) {
                if (a0) atomicOr(&remv[w0], a0);
                if (a1) atomicOr(&remv[w1], a1);
            }
        }
        __syncthreads();
        // ---- serial near-diag scan (thread 0, SMEM only)
        if (tid == 0) {
            u64 c0 = remv[w0];
            u64 c1 = remv[w1];
            u64 ext = 0ull;
            u64 nz0 = (u64)s_nz32[2 * w0] | ((u64)s_nz32[2 * w0 + 1] << 32);
            scan_word(sd2, w0 * 64, nz0, c0, c1);
            if (w1 < T) {
                u64 nz1 = (u64)s_nz32[2 * w1] | ((u64)s_nz32[2 * w1 + 1] << 32);
                scan_word(sd2, w1 * 64, nz1, c1, ext);
            }
            remv[w0] = c0;
            remv[w1] = c1;
            remv[w1 + 1] |= ext;
        }
        __syncthreads();
    }

    // output: kept -> [x1,y1,x2,y2,score], else zeros
    for (int p = tid; p < N; p += NT) {
        bool kept = (p < V) && !((remv[p >> 6] >> (p & 63)) & 1ull);
        float4 b = kept ? g_sbox[p] : make_float4(0.f, 0.f, 0.f, 0.f);
        float s = kept ? g_sscore[p] : 0.f;
        out[p * 5 + 0] = b.x;
        out[p * 5 + 1] = b.y;
        out[p * 5 + 2] = b.z;
        out[p * 5 + 3] = b.w;
        out[p * 5 + 4] = s;
    }

    // reset persistent state for the next graph replay
    __syncthreads();
    if (tid == 0) {
        while (*(volatile int*)&g_bar_exit < GRID - 1) { }
        g_bar_exit = 0;
        g_bar_arrive = 0;
        g_bar_release = 0;
        g_vcount = 0;
        __threadfence();
    }
}

extern "C" void kernel_launch(void* const* d_in, const int* in_sizes, int n_in,
                              void* d_out, int out_size) {
    const float* in = (const float*)d_in[0];
    float* out = (float*)d_out;
    cudaFuncSetAttribute(k_all, cudaFuncAttributeMaxDynamicSharedMemorySize,
                         NPAD * 16);   // 135,168B
    k_all<<<GRID, NT, NPAD * 16>>>(in, out);
}

// round 15
// speedup vs baseline: 1.1276x; 1.1276x over previous
#include <cuda_runtime.h>
#include <cstdint>

#define N 8400
#define WORDS 132          // ceil(8400/64)
#define SCORE_THR 0.5f
#define IOU_THR 0.5f
#define GRID 136           // <= 148 SMs: all blocks co-resident (wave 1)
#define NT 1024
#define JS 32              // rank j-split
#define NPAD 8448          // = 264*32

typedef unsigned long long u64;

struct __align__(16) SpEnt { u64 bits; u64 idx; };

// ---- persistent device state (allocation-free rule) ----
__device__ int g_vcount = 0;
__device__ int g_bar_arrive = 0;
__device__ volatile int g_bar_release = 0;
__device__ int g_bar_exit = 0;
__device__ u64 g_vkey[N];
__device__ float4 g_vbox[N];
__device__ float g_vscore[N];
__device__ int g_rankp[JS][N];
__device__ float4 g_sbox[N];
__device__ float g_sscore[N];
__device__ u64 g_diag2[NPAD][2];           // dense near-diag: own word, next word
__device__ unsigned g_scount[NPAD];        // # sparse entries (wg >= own+2)
__device__ SpEnt g_slist[N][WORDS];        // sparse far-off-diag words (CSR)

// Software grid barrier (all CTAs co-resident since GRID < #SMs).
// nanosleep backoff keeps waiting CTAs off the L2 while workers finish.
__device__ __forceinline__ void gbar(int gen) {
    __syncthreads();
    if (threadIdx.x == 0) {
        __threadfence();
        int prev = atomicAdd(&g_bar_arrive, 1);
        if (prev == gen * GRID - 1) {
            g_bar_release = gen;
        } else {
            while (g_bar_release < gen) { __nanosleep(128); }
        }
        __threadfence();
    }
    __syncthreads();
}

__device__ __forceinline__ void cpa16(uint32_t saddr, const void* gptr) {
    asm volatile("cp.async.cg.shared.global [%0], [%1], 16;"
                 :: "r"(saddr), "l"(gptr));
}

// batched greedy scan of one 64-row word; kept bit b ORs d0 -> cown, d1 -> cnext
__device__ __forceinline__ void scan_word(const u64 (*sd2)[2], int base, u64 nz,
                                          u64& cown, u64& cnext) {
    u64 cand = nz & ~cown;
    while (cand) {
        int bs[8]; u64 v0[8], v1[8];
        u64 tmp = cand; int m = 0;
#pragma unroll
        for (int k = 0; k < 8; ++k) {
            if (tmp) { bs[k] = __ffsll(tmp) - 1; tmp &= tmp - 1; m = k + 1; }
            else     { bs[k] = 0; }
        }
#pragma unroll
        for (int k = 0; k < 8; ++k) {
            v0[k] = (k < m) ? sd2[base + bs[k]][0] : 0ull;
            v1[k] = (k < m) ? sd2[base + bs[k]][1] : 0ull;
        }
#pragma unroll
        for (int k = 0; k < 8; ++k)
            if (k < m && !((cown >> bs[k]) & 1ull)) { cown |= v0[k]; cnext |= v1[k]; }
        int blast = bs[m - 1];
        u64 below = (blast == 63) ? ~0ull : ((2ull << blast) - 1ull);
        cand = nz & ~cown & ~below;
    }
}

__global__ __launch_bounds__(NT) void k_all(const float* __restrict__ in,
                                            float* __restrict__ out) {
    extern __shared__ __align__(16) char dyn[];   // 168,960B
    __shared__ u64 remv[WORDS + 2];
    __shared__ unsigned s_nz32[2 * WORDS];
    int tid = threadIdx.x;
    int bid = blockIdx.x;
    int gtid = bid * NT + tid;

    // ---------------- Phase 1: decode + compact valid ----------------------
    {
        int a = gtid;
        int lane = tid & 31;
        bool valid = false;
        float4 b = make_float4(0.f, 0.f, 0.f, 0.f);
        float s = 0.f;
        u64 key = 0ull;
        if (a < N) {
            float cx = in[a];
            float cy = in[N + a];
            float w  = in[2 * N + a];
            float h  = in[3 * N + a];
            s = in[4 * N + a];
            float hw = __fmul_rn(w, 0.5f);
            float hh = __fmul_rn(h, 0.5f);
            b.x = __fsub_rn(cx, hw);
            b.y = __fsub_rn(cy, hh);
            b.z = __fadd_rn(cx, hw);
            b.w = __fadd_rn(cy, hh);
            valid = (s >= SCORE_THR);
            key = (((u64)__float_as_uint(s)) << 14) | (u64)(16383 - a);
            g_scount[a] = 0u;
            g_diag2[a][0] = 0ull;
            g_diag2[a][1] = 0ull;
        }
        unsigned m = __ballot_sync(0xffffffffu, valid);
        if (m != 0u) {
            int leader = __ffs(m) - 1;
            int base = 0;
            if (lane == leader) base = atomicAdd(&g_vcount, __popc(m));
            base = __shfl_sync(0xffffffffu, base, leader);
            if (valid) {
                int pos = base + __popc(m & ((1u << lane) - 1u));
                g_vkey[pos]   = key;
                g_vbox[pos]   = b;
                g_vscore[pos] = s;
            }
        }
    }
    gbar(1);
    int V = *(volatile int*)&g_vcount;

    // ---------------- Phase 2: rank partials (i-blocks x 32 j-chunks) ------
    {
        u64* sk = (u64*)dyn;
        int IB = (V + NT - 1) / NT;
        int CH = (V + JS - 1) / JS;
        int ntasks = IB * JS;
        for (int task = bid; task < ntasks; task += GRID) {
            int ib = task % IB;
            int jb = task / IB;
            int jlo = jb * CH;
            int mlen = min(jlo + CH, V) - jlo;
            __syncthreads();
            for (int d = tid; d < mlen; d += NT)
                sk[d] = g_vkey[jlo + d];
            __syncthreads();
            int p = ib * NT + tid;
            u64 kp = (p < V) ? g_vkey[p] : 0ull;
            int cnt = 0;
#pragma unroll 8
            for (int d = 0; d < mlen; ++d)
                cnt += (sk[d] > kp) ? 1 : 0;
            if (p < V) g_rankp[jb][p] = cnt;
        }
    }
    gbar(2);

    // ---------------- Phase 3: sum partials + scatter -----------------------
    for (int p = gtid; p < V; p += GRID * NT) {
        int r = 0;
#pragma unroll
        for (int y = 0; y < JS; ++y) r += g_rankp[y][p];
        g_sbox[r]   = g_vbox[p];
        g_sscore[r] = g_vscore[p];
    }
    gbar(3);

    // ---------------- Phase 4: IoU -> diag2 + CSR far entries --------------
    // Half-block tasks: each 512-thread half processes an independent
    // 128-row x 256-col tile -> 2x shorter critical path than 128x512 tasks.
    {
        int h  = tid >> 9;                         // half: 0 or 1
        int ht = tid & 511;
        float4* cbox  = (float4*)(dyn + h * 5120); // 256 boxes per half
        float*  carea = (float*)(dyn + h * 5120 + 4096);
        int TvR = (V + 127) >> 7;                  // 128-row groups
        int TvC = (V + 255) >> 8;                  // 256-col groups
        int ntasks = 0;
        for (int rb = 0; rb < TvR; ++rb) ntasks += TvC - (rb >> 1);
        int rounds = (ntasks + 2 * GRID - 1) / (2 * GRID);
        for (int rd = 0; rd < rounds; ++rd) {
            int task = rd * 2 * GRID + bid * 2 + h;
            bool live = (task < ntasks);
            int rb = 0, cB = 0;
            if (live) {
                int rem = task;
                while (rem >= TvC - (rb >> 1)) { rem -= TvC - (rb >> 1); rb++; }
                cB = (rb >> 1) + rem;
            }
            __syncthreads();                       // protect smem reuse
            if (live && ht < 256) {
                int j = cB * 256 + ht;
                if (j < V) {
                    float4 b = g_sbox[j];
                    cbox[ht] = b;
                    carea[ht] = __fmul_rn(__fsub_rn(b.z, b.x),
                                          __fsub_rn(b.w, b.y));
                } else {
                    cbox[ht] = make_float4(0.f, 0.f, 0.f, 0.f);
                    carea[ht] = 0.f;
                }
            }
            __syncthreads();
            if (live) {
                int row = ht & 127;
                int wq  = ht >> 7;                 // 0..3
                int i = rb * 128 + row;
                int wg = cB * 4 + wq;              // global mask word
                int dstart = max(0, i + 1 - wg * 64);
                if (i < V && dstart < 64) {
                    float4 bi = g_sbox[i];
                    float ai = __fmul_rn(__fsub_rn(bi.z, bi.x),
                                         __fsub_rn(bi.w, bi.y));
                    int cbase = wq * 64;
                    u64 bits = 0ull;
                    for (int d = dstart; d < 64; ++d) {
                        float4 bj = cbox[cbase + d];
                        float ltx = fmaxf(bi.x, bj.x);
                        float lty = fmaxf(bi.y, bj.y);
                        float rbx = fminf(bi.z, bj.z);
                        float rby = fminf(bi.w, bj.w);
                        float wx = fmaxf(__fsub_rn(rbx, ltx), 0.0f);
                        float wy = fmaxf(__fsub_rn(rby, lty), 0.0f);
                        float inter = __fmul_rn(wx, wy);
                        float uni = __fsub_rn(__fadd_rn(ai, carea[cbase + d]),
                                              inter);
                        float den = fmaxf(uni, 1e-9f);
                        // exact lower screen: 0.5*den is exact; rn-div is
                        // monotone with rn(0.5)=0.5 => ratio<=0.5 -> not hit
                        float halfd = __fmul_rn(0.5f, den);
                        bool hit = false;
                        if (inter > halfd) {
                            if (inter > __fmul_rn(0.5005f, den)) hit = true;
                            else hit = (__fdiv_rn(inter, den) > IOU_THR);
                        }
                        if (hit) bits |= (1ull << d);
                    }
                    int own = i >> 6;
                    if (wg == own) {
                        g_diag2[i][0] = bits;
                    } else if (wg == own + 1) {
                        g_diag2[i][1] = bits;
                    } else if (bits) {
                        unsigned pos = atomicAdd(&g_scount[i], 1u);
                        SpEnt e; e.bits = bits; e.idx = (u64)wg;
                        g_slist[i][pos] = e;
                    }
                }
            }
        }
    }
    gbar(4);

    // ---------------- Phase 5: block 0 — supertile reduce + output ---------
    if (bid != 0) {
        __syncthreads();
        if (tid == 0) atomicAdd(&g_bar_exit, 1);
        return;
    }

    u64 (*sd2)[2] = (u64 (*)[2])dyn;               // [NPAD][2] 135,168B
    unsigned* sscnt = (unsigned*)(dyn + NPAD * 16);// [NPAD]     33,792B
    int T = (V + 63) >> 6;
    int TT = (T + 1) >> 1;
    __syncthreads();
    // init remv (incl. 2 spill words): bit p set iff p >= V
    for (int w = tid; w < WORDS + 2; w += NT) {
        int base = w * 64;
        u64 m;
        if (base + 64 <= V)      m = 0ull;
        else if (base >= V)      m = ~0ull;
        else                     m = (~0ull) << (V - base);
        remv[w] = m;
    }
    // one-shot staging: diag2 rows [0,V) + scount
    {
        for (int u = tid; u < V; u += NT)
            cpa16((uint32_t)__cvta_generic_to_shared(&sd2[u][0]), &g_diag2[u][0]);
        int ns = (V + 3) >> 2;
        for (int u = tid; u < ns; u += NT)
            cpa16((uint32_t)__cvta_generic_to_shared(&sscnt[u * 4]),
                  &g_scount[u * 4]);
        asm volatile("cp.async.commit_group;");
        asm volatile("cp.async.wait_group 0;" ::: "memory");
    }
    __syncthreads();
    // nz bitmap over (d0|d1), bounded to NPAD
    for (int c = 0; c < NPAD; c += NT) {
        int r = c + tid;
        bool nzb = (r < V) && ((sd2[r][0] | sd2[r][1]) != 0ull);
        unsigned bal = __ballot_sync(0xffffffffu, nzb);
        if ((tid & 31) == 0 && r < NPAD) s_nz32[r >> 5] = bal;
    }
    __syncthreads();

    for (int t = 0; t < TT; ++t) {
        int w0 = 2 * t, w1 = 2 * t + 1;
        if (tid == 0) {
            u64 c0 = remv[w0];
            u64 c1 = remv[w1];
            u64 ext = 0ull;
            u64 nz0 = (u64)s_nz32[2 * w0] | ((u64)s_nz32[2 * w0 + 1] << 32);
            scan_word(sd2, w0 * 64, nz0, c0, c1);
            if (w1 < T) {
                u64 nz1 = (u64)s_nz32[2 * w1] | ((u64)s_nz32[2 * w1 + 1] << 32);
                scan_word(sd2, w1 * 64, nz1, c1, ext);
            }
            remv[w0] = c0;
            remv[w1] = c1;
            remv[w1 + 1] |= ext;
        }
        __syncthreads();
        // OR phase: 128 rows x 8 threads; all entries target words > w1
        {
            int rr = tid >> 3;                      // 0..127
            int sub = tid & 7;
            int r = w0 * 64 + rr;
            u64 curw = remv[w0 + (rr >> 6)];
            if (r < V && !((curw >> (r & 63)) & 1ull)) {   // row kept
                int cnt = (int)sscnt[r];
                const SpEnt* lp = &g_slist[r][0];
                for (int e = sub; e < cnt; e += 8) {
                    ulonglong2 ent = *(const ulonglong2*)&lp[e];  // LDG.128
                    atomicOr(&remv[(int)ent.y], ent.x);
                }
            }
        }
        __syncthreads();
    }

    // output: kept -> [x1,y1,x2,y2,score], else zeros
    for (int p = tid; p < N; p += NT) {
        bool kept = (p < V) && !((remv[p >> 6] >> (p & 63)) & 1ull);
        float4 b = kept ? g_sbox[p] : make_float4(0.f, 0.f, 0.f, 0.f);
        float s = kept ? g_sscore[p] : 0.f;
        out[p * 5 + 0] = b.x;
        out[p * 5 + 1] = b.y;
        out[p * 5 + 2] = b.z;
        out[p * 5 + 3] = b.w;
        out[p * 5 + 4] = s;
    }

    // reset persistent state for the next graph replay
    __syncthreads();
    if (tid == 0) {
        while (*(volatile int*)&g_bar_exit < GRID - 1) { __nanosleep(128); }
        g_bar_exit = 0;
        g_bar_arrive = 0;
        g_bar_release = 0;
        g_vcount = 0;
        __threadfence();
    }
}

extern "C" void kernel_launch(void* const* d_in, const int* in_sizes, int n_in,
                              void* d_out, int out_size) {
    const float* in = (const float*)d_in[0];
    float* out = (float*)d_out;
    cudaFuncSetAttribute(k_all, cudaFuncAttributeMaxDynamicSharedMemorySize,
                         NPAD * 20);   // 168,960B
    k_all<<<GRID, NT, NPAD * 20>>>(in, out);
}